// round 2
// baseline (speedup 1.0000x reference)
#include <cuda_runtime.h>
#include <cuda_bf16.h>
#include <cstdint>

#define N_X   4096
#define M_SV  8192
#define D_DIM 512

#define TILE_M   128
#define TILE_N   128
#define K_CHUNK  64
#define N_CHUNKS (D_DIM / K_CHUNK)   // 8
#define NPART    (M_SV / TILE_N)     // 64

// ---- scratch in device globals (no allocation allowed) ----
__device__ __nv_bfloat16 g_Xb[N_X * D_DIM];
__device__ __nv_bfloat16 g_SVb[M_SV * D_DIM];
__device__ float g_fx[N_X];              // exp(-gamma * ||x_n||^2)
__device__ float g_w[M_SV];              // DC[m] * exp(-gamma * ||sv_m||^2)
__device__ float g_part[NPART * N_X];    // split-N partials (deterministic)

// ---- dynamic smem layout (relative to 1024B-aligned base) ----
#define STAGE_BYTES 32768      // A tile 16KB + B tile 16KB
#define OFF_BSTAGE  16384
#define OFF_W       65536      // 128 floats
#define OFF_RED     66048      // 256 floats
#define SMEM_BYTES  (66048 + 1024 + 1024)   // + align slack

// ============================ helpers ============================
__device__ __forceinline__ uint32_t smem_u32(const void* p) {
    uint32_t a;
    asm("{ .reg .u64 t; cvta.to.shared.u64 t, %1; cvt.u32.u64 %0, t; }" : "=r"(a) : "l"(p));
    return a;
}
__device__ __forceinline__ float ex2f(float x) {
    float y; asm("ex2.approx.ftz.f32 %0, %1;" : "=f"(y) : "f"(x)); return y;
}
__device__ __forceinline__ void cpasync16(uint32_t dst, const void* src) {
    asm volatile("cp.async.cg.shared.global [%0], [%1], 16;" :: "r"(dst), "l"(src) : "memory");
}
#define CP_COMMIT() asm volatile("cp.async.commit_group;" ::: "memory")
#define CP_WAIT(n)  asm volatile("cp.async.wait_group %0;" :: "n"(n) : "memory")

__device__ __forceinline__ void ldsm4(uint32_t* r, uint32_t addr) {
    asm volatile("ldmatrix.sync.aligned.m8n8.x4.shared.b16 {%0,%1,%2,%3}, [%4];"
                 : "=r"(r[0]), "=r"(r[1]), "=r"(r[2]), "=r"(r[3]) : "r"(addr));
}
__device__ __forceinline__ void mma16816(float* c, const uint32_t* a, uint32_t b0, uint32_t b1) {
    asm volatile("mma.sync.aligned.m16n8k16.row.col.f32.bf16.bf16.f32 "
                 "{%0,%1,%2,%3}, {%4,%5,%6,%7}, {%8,%9}, {%0,%1,%2,%3};"
                 : "+f"(c[0]), "+f"(c[1]), "+f"(c[2]), "+f"(c[3])
                 : "r"(a[0]), "r"(a[1]), "r"(a[2]), "r"(a[3]), "r"(b0), "r"(b1));
}
__device__ __forceinline__ uint32_t sw128(uint32_t off) { return off ^ ((off >> 3) & 0x70); }

// ============================ prep kernel ============================
// One 128-thread block per row: sum-of-squares, fp32->bf16 convert, fx/w.
__global__ void prep_kernel(const float* __restrict__ X, const float* __restrict__ SV,
                            const float* __restrict__ DC, const float* __restrict__ gammaPtr) {
    __shared__ float warp_s[4];
    int row = blockIdx.x;
    int t = threadIdx.x;  // 0..127
    float g = gammaPtr[0];

    const float* src;
    __nv_bfloat16* dst;
    if (row < N_X) { src = X + (size_t)row * D_DIM;  dst = g_Xb  + (size_t)row * D_DIM; }
    else           { int m = row - N_X;
                     src = SV + (size_t)m * D_DIM;   dst = g_SVb + (size_t)m * D_DIM; }

    float4 v = reinterpret_cast<const float4*>(src)[t];
    float ss = v.x * v.x + v.y * v.y + v.z * v.z + v.w * v.w;

    __nv_bfloat162* d2 = reinterpret_cast<__nv_bfloat162*>(dst);
    d2[t * 2 + 0] = __floats2bfloat162_rn(v.x, v.y);
    d2[t * 2 + 1] = __floats2bfloat162_rn(v.z, v.w);

    #pragma unroll
    for (int o = 16; o > 0; o >>= 1) ss += __shfl_xor_sync(0xFFFFFFFFu, ss, o);
    if ((t & 31) == 0) warp_s[t >> 5] = ss;
    __syncthreads();
    if (t == 0) {
        float s = warp_s[0] + warp_s[1] + warp_s[2] + warp_s[3];
        float e = __expf(-g * s);
        if (row < N_X) g_fx[row] = e;
        else           g_w[row - N_X] = DC[row - N_X] * e;
    }
}

// ============================ main GEMM+epilogue ============================
// Grid (32, 64): blockIdx.x -> M tile (128 X rows), blockIdx.y -> N tile (128 SVs).
// 8 warps as 4 (M) x 2 (N); warp tile 32x64.
__global__ __launch_bounds__(256, 2)
void rbf_main(const float* __restrict__ gammaPtr) {
    extern __shared__ char smem_raw[];
    char* smb = (char*)((((uintptr_t)smem_raw) + 1023) & ~(uintptr_t)1023);
    uint32_t sb = (smem_u32(smem_raw) + 1023u) & ~1023u;

    const int tid  = threadIdx.x;
    const int lane = tid & 31;
    const int wid  = tid >> 5;
    const int warpM = wid & 3;   // 0..3
    const int warpN = wid >> 2;  // 0..1
    const int m0 = blockIdx.x * TILE_M;
    const int n0 = blockIdx.y * TILE_N;

    if (tid < 128) reinterpret_cast<float*>(smb + OFF_W)[tid] = g_w[n0 + tid];

    const uint4* X4  = reinterpret_cast<const uint4*>(g_Xb);   // 64 x 16B per row
    const uint4* SV4 = reinterpret_cast<const uint4*>(g_SVb);

    // ---- async stage loader: 4 A chunks + 4 B chunks per thread ----
    auto issue_load = [&](int stage, int ks) {
        uint32_t sA = sb + stage * STAGE_BYTES;
        uint32_t sB = sA + OFF_BSTAGE;
        #pragma unroll
        for (int i = 0; i < 4; ++i) {
            int q = tid + i * 256;           // 0..1023
            int row = q >> 3, c = q & 7;
            cpasync16(sA + sw128(row * 128 + c * 16),
                      &X4[(size_t)(m0 + row) * 64 + ks * 8 + c]);
        }
        #pragma unroll
        for (int i = 0; i < 4; ++i) {
            int q = tid + i * 256;
            int row = q >> 3, c = q & 7;
            cpasync16(sB + sw128(row * 128 + c * 16),
                      &SV4[(size_t)(n0 + row) * 64 + ks * 8 + c]);
        }
        CP_COMMIT();
    };

    float acc[2][8][4];
    #pragma unroll
    for (int a = 0; a < 2; ++a)
        #pragma unroll
        for (int b = 0; b < 8; ++b)
            #pragma unroll
            for (int c = 0; c < 4; ++c) acc[a][b][c] = 0.0f;

    issue_load(0, 0);

    // precompute per-lane fragment address pieces
    // A: row = warpM*32 + mf*16 + (lane&15); colByte = kstep*32 + ((lane>>4)&1)*16
    // B: row = warpN*64 + nfp*16 + ((lane&16)>>1) + (lane&7); colByte = kstep*32 + ((lane>>3)&1)*16
    const int arow = warpM * 32 + (lane & 15);
    const uint32_t acb = ((lane >> 4) & 1) * 16;
    const int brow0 = warpN * 64 + ((lane & 16) >> 1) + (lane & 7);
    const uint32_t bcb = ((lane >> 3) & 1) * 16;

    #pragma unroll 1
    for (int ks = 0; ks < N_CHUNKS; ++ks) {
        int cur = ks & 1;
        if (ks + 1 < N_CHUNKS) { issue_load(cur ^ 1, ks + 1); CP_WAIT(1); }
        else                   { CP_WAIT(0); }
        __syncthreads();

        uint32_t sA = sb + cur * STAGE_BYTES;
        uint32_t sB = sA + OFF_BSTAGE;

        #pragma unroll
        for (int kstep = 0; kstep < 4; ++kstep) {
            uint32_t kc = (uint32_t)kstep * 32;
            uint32_t a[2][4];
            #pragma unroll
            for (int mf = 0; mf < 2; ++mf) {
                int row = arow + mf * 16;
                uint32_t addr = sA + row * 128 + ((kc + acb) ^ ((row & 7) << 4));
                ldsm4(a[mf], addr);
            }
            uint32_t b[4][4];
            #pragma unroll
            for (int nfp = 0; nfp < 4; ++nfp) {
                int row = brow0 + nfp * 16;
                uint32_t addr = sB + row * 128 + ((kc + bcb) ^ ((row & 7) << 4));
                ldsm4(b[nfp], addr);
            }
            #pragma unroll
            for (int mf = 0; mf < 2; ++mf)
                #pragma unroll
                for (int nfp = 0; nfp < 4; ++nfp) {
                    mma16816(acc[mf][2 * nfp + 0], a[mf], b[nfp][0], b[nfp][1]);
                    mma16816(acc[mf][2 * nfp + 1], a[mf], b[nfp][2], b[nfp][3]);
                }
        }
        __syncthreads();   // stage reuse guard
    }

    // ---- epilogue: sum_n w[n] * exp2(c2 * cross) per output row ----
    float c2 = 2.0f * gammaPtr[0] * 1.44269504f;
    const float2* wt = reinterpret_cast<const float2*>(smb + OFF_W);
    float2 wv[8];
    #pragma unroll
    for (int nf = 0; nf < 8; ++nf)
        wv[nf] = wt[warpN * 32 + nf * 4 + (lane & 3)];

    float rsum[2][2] = {{0.0f, 0.0f}, {0.0f, 0.0f}};
    #pragma unroll
    for (int mf = 0; mf < 2; ++mf)
        #pragma unroll
        for (int nf = 0; nf < 8; ++nf) {
            rsum[mf][0] = fmaf(wv[nf].x, ex2f(acc[mf][nf][0] * c2), rsum[mf][0]);
            rsum[mf][0] = fmaf(wv[nf].y, ex2f(acc[mf][nf][1] * c2), rsum[mf][0]);
            rsum[mf][1] = fmaf(wv[nf].x, ex2f(acc[mf][nf][2] * c2), rsum[mf][1]);
            rsum[mf][1] = fmaf(wv[nf].y, ex2f(acc[mf][nf][3] * c2), rsum[mf][1]);
        }

    float* red = reinterpret_cast<float*>(smb + OFF_RED);
    #pragma unroll
    for (int mf = 0; mf < 2; ++mf)
        #pragma unroll
        for (int h = 0; h < 2; ++h) {
            float v = rsum[mf][h];
            v += __shfl_xor_sync(0xFFFFFFFFu, v, 1);
            v += __shfl_xor_sync(0xFFFFFFFFu, v, 2);
            if ((lane & 3) == 0) {
                int rowLocal = warpM * 32 + mf * 16 + h * 8 + (lane >> 2);
                red[warpN * 128 + rowLocal] = v;
            }
        }
    __syncthreads();
    if (tid < 128)
        g_part[(size_t)blockIdx.y * N_X + m0 + tid] = red[tid] + red[128 + tid];
}

// ============================ final reduce ============================
__global__ void reduce_kernel(const float* __restrict__ IC, float* __restrict__ out) {
    int i = blockIdx.x * 256 + threadIdx.x;
    float s = 0.0f;
    #pragma unroll
    for (int j = 0; j < NPART; ++j) s += g_part[(size_t)j * N_X + i];
    out[i] = fmaf(g_fx[i], s, IC[0]);
}

// ============================ launch ============================
extern "C" void kernel_launch(void* const* d_in, const int* in_sizes, int n_in,
                              void* d_out, int out_size) {
    (void)in_sizes; (void)n_in; (void)out_size;
    const float* X     = (const float*)d_in[0];
    const float* SV    = (const float*)d_in[1];
    const float* DC    = (const float*)d_in[2];
    const float* IC    = (const float*)d_in[3];
    const float* gamma = (const float*)d_in[4];
    float* out = (float*)d_out;

    cudaFuncSetAttribute(rbf_main, cudaFuncAttributeMaxDynamicSharedMemorySize, SMEM_BYTES);

    prep_kernel<<<N_X + M_SV, 128>>>(X, SV, DC, gamma);
    rbf_main<<<dim3(N_X / TILE_M, M_SV / TILE_N), 256, SMEM_BYTES>>>(gamma);
    reduce_kernel<<<N_X / 256, 256>>>(IC, out);
}